// round 3
// baseline (speedup 1.0000x reference)
#include <cuda_runtime.h>

#define UL unsigned long long

// Scratch (no allocs allowed): projections and h-split partials.
__device__ float g_ab[2 * 512 * 768];            // [z][b*S+row][H]  (z=0: ha+b1, z=1: hb)
__device__ float g_part[8 * 4 * 128 * 128 * 2];  // [hsplit][b][s][t][o]

__device__ __forceinline__ UL pack_dup(float x) {
    unsigned xi = __float_as_uint(x);
    UL r; asm("mov.b64 %0, {%1, %1};" : "=l"(r) : "r"(xi)); return r;
}
__device__ __forceinline__ UL fma2(UL a, UL b, UL c) {
    UL d; asm("fma.rn.f32x2 %0, %1, %2, %3;" : "=l"(d) : "l"(a), "l"(b), "l"(c)); return d;
}
__device__ __forceinline__ UL add2(UL a, UL b) {
    UL d; asm("add.rn.f32x2 %0, %1, %2;" : "=l"(d) : "l"(a), "l"(b)); return d;
}

// ---------------------------------------------------------------------------
// Projection GEMM: C[z][m][n] = sum_k A_z[m][k] * W1[z*768 + k][n] (+ b1[n] if z==0)
// Tile 128(M) x 64(N), 128 threads, per-thread 8x8 via packed f32x2 FMA.
// Grid: (4 m-tiles, 12 n-tiles, 2) = 96 blocks -> one wave on 148 SMs.
// ---------------------------------------------------------------------------
__global__ __launch_bounds__(128) void proj_kernel(
    const float* __restrict__ a_in, const float* __restrict__ b_in,
    const float* __restrict__ W1,   const float* __restrict__ b1)
{
    const int z = blockIdx.z;
    const float* __restrict__ A = z ? b_in : a_in;
    const float* __restrict__ W = W1 + z * 768 * 768;
    float* C = g_ab + z * 512 * 768;
    const int m0 = blockIdx.x * 128;
    const int n0 = blockIdx.y * 64;

    __shared__ float As[16][132];   // transposed A tile, padded (132*4 = 16B aligned rows)
    __shared__ float Bs[16][64];

    const int tid = threadIdx.x;
    const int tn = tid & 7;         // 8 n-groups of 8
    const int tm = tid >> 3;        // 16 m-groups of 8

    UL acc[8][4];
    #pragma unroll
    for (int i = 0; i < 8; i++)
        #pragma unroll
        for (int j = 0; j < 4; j++) acc[i][j] = 0ull;

    // Prefetch registers for the next K-tile (hides LDG latency under compute).
    float4 pa[4], pb[2];
    {
        const float* ar = A + (m0 + tid) * 768;
        #pragma unroll
        for (int q = 0; q < 4; q++) pa[q] = *(const float4*)(ar + q * 4);
        #pragma unroll
        for (int i = 0; i < 2; i++) {
            int f = tid + i * 128; int kr = f >> 4; int nc = (f & 15) * 4;
            pb[i] = *(const float4*)(W + kr * 768 + n0 + nc);
        }
    }

    #pragma unroll 1
    for (int kb = 0; kb < 768; kb += 16) {
        __syncthreads();
        #pragma unroll
        for (int q = 0; q < 4; q++) {
            As[q * 4 + 0][tid] = pa[q].x;
            As[q * 4 + 1][tid] = pa[q].y;
            As[q * 4 + 2][tid] = pa[q].z;
            As[q * 4 + 3][tid] = pa[q].w;
        }
        #pragma unroll
        for (int i = 0; i < 2; i++) {
            int f = tid + i * 128; int kr = f >> 4; int nc = (f & 15) * 4;
            *(float4*)&Bs[kr][nc] = pb[i];
        }
        __syncthreads();

        if (kb + 16 < 768) {
            const float* ar = A + (m0 + tid) * 768 + kb + 16;
            #pragma unroll
            for (int q = 0; q < 4; q++) pa[q] = *(const float4*)(ar + q * 4);
            #pragma unroll
            for (int i = 0; i < 2; i++) {
                int f = tid + i * 128; int kr = f >> 4; int nc = (f & 15) * 4;
                pb[i] = *(const float4*)(W + (kb + 16 + kr) * 768 + n0 + nc);
            }
        }

        #pragma unroll
        for (int k = 0; k < 16; k++) {
            float4 alo = *(const float4*)&As[k][tm * 8];
            float4 ahi = *(const float4*)&As[k][tm * 8 + 4];
            UL bv0 = *(const UL*)&Bs[k][tn * 8];
            UL bv1 = *(const UL*)&Bs[k][tn * 8 + 2];
            UL bv2 = *(const UL*)&Bs[k][tn * 8 + 4];
            UL bv3 = *(const UL*)&Bs[k][tn * 8 + 6];
            float av[8] = {alo.x, alo.y, alo.z, alo.w, ahi.x, ahi.y, ahi.z, ahi.w};
            #pragma unroll
            for (int i = 0; i < 8; i++) {
                UL aa = pack_dup(av[i]);
                acc[i][0] = fma2(aa, bv0, acc[i][0]);
                acc[i][1] = fma2(aa, bv1, acc[i][1]);
                acc[i][2] = fma2(aa, bv2, acc[i][2]);
                acc[i][3] = fma2(aa, bv3, acc[i][3]);
            }
        }
    }

    #pragma unroll
    for (int i = 0; i < 8; i++) {
        int m = m0 + tm * 8 + i;
        #pragma unroll
        for (int j = 0; j < 4; j++) {
            int n = n0 + tn * 8 + j * 2;
            UL v = acc[i][j];
            if (z == 0) v = add2(v, *(const UL*)(b1 + n));  // fold bias into ha
            *(UL*)(C + m * 768 + n) = v;
        }
    }
}

// ---------------------------------------------------------------------------
// Pairwise epilogue: part[hz][b][s][t][o] = sum_{h in chunk} relu(ha[s][h]+hb[t][h]) * W2[h][o]
// 64x64 (s,t) tile, 256 threads, per-thread 4x4 pairs, H split 8 ways (chunk=96).
// Grid: (4 tiles, 4 batch, 8 hsplit) = 128 blocks -> one wave.
// ---------------------------------------------------------------------------
__global__ __launch_bounds__(256) void pair_kernel(const float* __restrict__ W2)
{
    const int bx = blockIdx.x;           // 2 s-tiles x 2 t-tiles
    const int bb = blockIdx.y;           // batch
    const int bz = blockIdx.z;           // h split
    const int s0 = (bx & 1) * 64;
    const int t0 = (bx >> 1) * 64;
    const int h0 = bz * 96;

    const float* __restrict__ ha = g_ab + (bb * 128 + s0) * 768 + h0;
    const float* __restrict__ hb = g_ab + 512 * 768 + (bb * 128 + t0) * 768 + h0;

    __shared__ float  sha[32][68];       // [k][s], padded (68*4 = 16B aligned rows)
    __shared__ float  shb[32][68];       // [k][t]
    __shared__ float2 sw2[32];

    const int tid = threadIdx.x;
    const int tx = tid & 15;             // 16 t-groups of 4
    const int ty = tid >> 4;             // 16 s-groups of 4

    float acc[4][4][2];
    #pragma unroll
    for (int i = 0; i < 4; i++)
        #pragma unroll
        for (int j = 0; j < 4; j++) { acc[i][j][0] = 0.f; acc[i][j][1] = 0.f; }

    #pragma unroll 1
    for (int kb = 0; kb < 96; kb += 32) {
        __syncthreads();
        #pragma unroll
        for (int i = 0; i < 2; i++) {
            int f = tid + i * 256;
            int si = f & 63;
            int kq = (f >> 6) * 4;
            float4 v = *(const float4*)(ha + si * 768 + kb + kq);
            sha[kq + 0][si] = v.x; sha[kq + 1][si] = v.y;
            sha[kq + 2][si] = v.z; sha[kq + 3][si] = v.w;
            float4 w = *(const float4*)(hb + si * 768 + kb + kq);
            shb[kq + 0][si] = w.x; shb[kq + 1][si] = w.y;
            shb[kq + 2][si] = w.z; shb[kq + 3][si] = w.w;
        }
        if (tid < 32) sw2[tid] = *(const float2*)(W2 + (h0 + kb + tid) * 2);
        __syncthreads();

        #pragma unroll
        for (int k = 0; k < 32; k++) {
            float4 av = *(const float4*)&sha[k][ty * 4];
            float4 bv = *(const float4*)&shb[k][tx * 4];
            float2 w  = sw2[k];
            float aa[4] = {av.x, av.y, av.z, av.w};
            float bb4[4] = {bv.x, bv.y, bv.z, bv.w};
            #pragma unroll
            for (int i = 0; i < 4; i++)
                #pragma unroll
                for (int j = 0; j < 4; j++) {
                    float x = aa[i] + bb4[j];
                    float v = fmaxf(x, 0.0f);
                    acc[i][j][0] += v * w.x;
                    acc[i][j][1] += v * w.y;
                }
        }
    }

    float* P = g_part + (bz * 4 + bb) * (128 * 128 * 2);
    #pragma unroll
    for (int i = 0; i < 4; i++)
        #pragma unroll
        for (int j = 0; j < 4; j++) {
            int s = s0 + ty * 4 + i;
            int t = t0 + tx * 4 + j;
            *(float2*)(P + (s * 128 + t) * 2) = make_float2(acc[i][j][0], acc[i][j][1]);
        }
}

// ---------------------------------------------------------------------------
// Reduce the 8 h-split partials + output bias. Deterministic (no atomics).
// ---------------------------------------------------------------------------
__global__ void reduce_kernel(const float* __restrict__ b2, float* __restrict__ out)
{
    int idx = blockIdx.x * 256 + threadIdx.x;   // pair index 0..65535
    float2 acc = *(const float2*)b2;
    #pragma unroll
    for (int zz = 0; zz < 8; zz++) {
        float2 p = *(const float2*)(g_part + zz * (4 * 128 * 128 * 2) + idx * 2);
        acc.x += p.x; acc.y += p.y;
    }
    *(float2*)(out + idx * 2) = acc;
}

extern "C" void kernel_launch(void* const* d_in, const int* in_sizes, int n_in,
                              void* d_out, int out_size)
{
    const float* a  = (const float*)d_in[0];
    const float* b  = (const float*)d_in[1];
    const float* W1 = (const float*)d_in[2];
    const float* b1 = (const float*)d_in[3];
    const float* W2 = (const float*)d_in[4];
    const float* b2 = (const float*)d_in[5];
    float* out = (float*)d_out;

    proj_kernel<<<dim3(4, 12, 2), 128>>>(a, b, W1, b1);
    pair_kernel<<<dim3(4, 4, 8), 256>>>(W2);
    reduce_kernel<<<256, 256>>>(b2, out);
}

// round 4
// speedup vs baseline: 1.2812x; 1.2812x over previous
#include <cuda_runtime.h>

#define UL unsigned long long

// Scratch (no allocs allowed): projections and h-split partials.
__device__ float g_ab[2 * 512 * 768];            // [z][b*S+row][H]  (z=0: ha+b1, z=1: hb)
__device__ float g_part[8 * 4 * 128 * 128 * 2];  // [hsplit][b][s][t][o]

__device__ __forceinline__ UL pack_dup(float x) {
    unsigned xi = __float_as_uint(x);
    UL r; asm("mov.b64 %0, {%1, %1};" : "=l"(r) : "r"(xi)); return r;
}
__device__ __forceinline__ UL fma2(UL a, UL b, UL c) {
    UL d; asm("fma.rn.f32x2 %0, %1, %2, %3;" : "=l"(d) : "l"(a), "l"(b), "l"(c)); return d;
}
__device__ __forceinline__ UL add2(UL a, UL b) {
    UL d; asm("add.rn.f32x2 %0, %1, %2;" : "=l"(d) : "l"(a), "l"(b)); return d;
}

// ---------------------------------------------------------------------------
// Projection GEMM, retiled for occupancy:
//   C[z][m][n] = sum_k A_z[m][k] * W1[z*768 + k][n] (+ b1[n] if z==0)
// Tile 32(M) x 64(N), 128 threads, per-thread 4x4 via packed f32x2 FMA.
// z folded into m-grid: grid (32, 12) = 384 blocks (~2.6 blocks/SM, all SMs busy).
// ---------------------------------------------------------------------------
__global__ __launch_bounds__(128) void proj_kernel(
    const float* __restrict__ a_in, const float* __restrict__ b_in,
    const float* __restrict__ W1,   const float* __restrict__ b1)
{
    const int bx = blockIdx.x;            // 0..31 -> 16 m-tiles per z, 2 z
    const int z  = bx >> 4;
    const int m0 = (bx & 15) * 32;
    const int n0 = blockIdx.y * 64;

    const float* __restrict__ A = z ? b_in : a_in;
    const float* __restrict__ W = W1 + z * 768 * 768;
    float* C = g_ab + z * 512 * 768;

    __shared__ float As[16][36];          // transposed A tile, padded
    __shared__ float Bs[16][64];

    const int tid = threadIdx.x;
    const int tx = tid & 15;              // 16 n-groups of 4
    const int ty = tid >> 4;              // 8 m-groups of 4

    UL acc[4][2];
    #pragma unroll
    for (int i = 0; i < 4; i++) { acc[i][0] = 0ull; acc[i][1] = 0ull; }

    // A-load mapping: row = tid>>2 (0..31), kq = (tid&3)*4
    const int arow = tid >> 2;
    const int akq  = (tid & 3) * 4;
    // B-load mapping (2 float4 per thread)
    const int f0 = tid, f1 = tid + 128;
    const int kr0 = f0 >> 4, nc0 = (f0 & 15) * 4;
    const int kr1 = f1 >> 4, nc1 = (f1 & 15) * 4;

    // Prefetch first K-chunk.
    float4 pa = *(const float4*)(A + (m0 + arow) * 768 + akq);
    float4 pb0 = *(const float4*)(W + kr0 * 768 + n0 + nc0);
    float4 pb1 = *(const float4*)(W + kr1 * 768 + n0 + nc1);

    #pragma unroll 1
    for (int kb = 0; kb < 768; kb += 16) {
        __syncthreads();
        As[akq + 0][arow] = pa.x;
        As[akq + 1][arow] = pa.y;
        As[akq + 2][arow] = pa.z;
        As[akq + 3][arow] = pa.w;
        *(float4*)&Bs[kr0][nc0] = pb0;
        *(float4*)&Bs[kr1][nc1] = pb1;
        __syncthreads();

        if (kb + 16 < 768) {
            pa  = *(const float4*)(A + (m0 + arow) * 768 + kb + 16 + akq);
            pb0 = *(const float4*)(W + (kb + 16 + kr0) * 768 + n0 + nc0);
            pb1 = *(const float4*)(W + (kb + 16 + kr1) * 768 + n0 + nc1);
        }

        #pragma unroll
        for (int k = 0; k < 16; k++) {
            float4 av = *(const float4*)&As[k][ty * 4];
            UL bv0 = *(const UL*)&Bs[k][tx * 4];
            UL bv1 = *(const UL*)&Bs[k][tx * 4 + 2];
            float aa[4] = {av.x, av.y, av.z, av.w};
            #pragma unroll
            for (int i = 0; i < 4; i++) {
                UL ap = pack_dup(aa[i]);
                acc[i][0] = fma2(ap, bv0, acc[i][0]);
                acc[i][1] = fma2(ap, bv1, acc[i][1]);
            }
        }
    }

    #pragma unroll
    for (int i = 0; i < 4; i++) {
        int m = m0 + ty * 4 + i;
        int n = n0 + tx * 4;
        UL v0 = acc[i][0], v1 = acc[i][1];
        if (z == 0) {
            v0 = add2(v0, *(const UL*)(b1 + n));      // fold bias into ha
            v1 = add2(v1, *(const UL*)(b1 + n + 2));
        }
        *(UL*)(C + m * 768 + n)     = v0;
        *(UL*)(C + m * 768 + n + 2) = v1;
    }
}

// ---------------------------------------------------------------------------
// Pairwise epilogue: part[hz][b][s][t][o] = sum_{h in chunk} relu(ha[s][h]+hb[t][h]) * W2[h][o]
// 64x64 (s,t) tile, 256 threads, per-thread 4x4 pairs, H split 8 ways (chunk=96).
// Grid: (4 tiles, 4 batch, 8 hsplit) = 128 blocks -> one wave.
// ---------------------------------------------------------------------------
__global__ __launch_bounds__(256) void pair_kernel(const float* __restrict__ W2)
{
    const int bx = blockIdx.x;           // 2 s-tiles x 2 t-tiles
    const int bb = blockIdx.y;           // batch
    const int bz = blockIdx.z;           // h split
    const int s0 = (bx & 1) * 64;
    const int t0 = (bx >> 1) * 64;
    const int h0 = bz * 96;

    const float* __restrict__ ha = g_ab + (bb * 128 + s0) * 768 + h0;
    const float* __restrict__ hb = g_ab + 512 * 768 + (bb * 128 + t0) * 768 + h0;

    __shared__ float  sha[32][68];       // [k][s], padded
    __shared__ float  shb[32][68];       // [k][t]
    __shared__ float2 sw2[32];

    const int tid = threadIdx.x;
    const int tx = tid & 15;             // 16 t-groups of 4
    const int ty = tid >> 4;             // 16 s-groups of 4

    float acc[4][4][2];
    #pragma unroll
    for (int i = 0; i < 4; i++)
        #pragma unroll
        for (int j = 0; j < 4; j++) { acc[i][j][0] = 0.f; acc[i][j][1] = 0.f; }

    #pragma unroll 1
    for (int kb = 0; kb < 96; kb += 32) {
        __syncthreads();
        #pragma unroll
        for (int i = 0; i < 2; i++) {
            int f = tid + i * 256;
            int si = f & 63;
            int kq = (f >> 6) * 4;
            float4 v = *(const float4*)(ha + si * 768 + kb + kq);
            sha[kq + 0][si] = v.x; sha[kq + 1][si] = v.y;
            sha[kq + 2][si] = v.z; sha[kq + 3][si] = v.w;
            float4 w = *(const float4*)(hb + si * 768 + kb + kq);
            shb[kq + 0][si] = w.x; shb[kq + 1][si] = w.y;
            shb[kq + 2][si] = w.z; shb[kq + 3][si] = w.w;
        }
        if (tid < 32) sw2[tid] = *(const float2*)(W2 + (h0 + kb + tid) * 2);
        __syncthreads();

        #pragma unroll
        for (int k = 0; k < 32; k++) {
            float4 av = *(const float4*)&sha[k][ty * 4];
            float4 bv = *(const float4*)&shb[k][tx * 4];
            float2 w  = sw2[k];
            float aa[4] = {av.x, av.y, av.z, av.w};
            float bb4[4] = {bv.x, bv.y, bv.z, bv.w};
            #pragma unroll
            for (int i = 0; i < 4; i++)
                #pragma unroll
                for (int j = 0; j < 4; j++) {
                    float x = aa[i] + bb4[j];
                    float v = fmaxf(x, 0.0f);
                    acc[i][j][0] += v * w.x;
                    acc[i][j][1] += v * w.y;
                }
        }
    }

    float* P = g_part + (bz * 4 + bb) * (128 * 128 * 2);
    #pragma unroll
    for (int i = 0; i < 4; i++)
        #pragma unroll
        for (int j = 0; j < 4; j++) {
            int s = s0 + ty * 4 + i;
            int t = t0 + tx * 4 + j;
            *(float2*)(P + (s * 128 + t) * 2) = make_float2(acc[i][j][0], acc[i][j][1]);
        }
}

// ---------------------------------------------------------------------------
// Reduce the 8 h-split partials + output bias. Deterministic (no atomics).
// ---------------------------------------------------------------------------
__global__ void reduce_kernel(const float* __restrict__ b2, float* __restrict__ out)
{
    int idx = blockIdx.x * 256 + threadIdx.x;   // pair index 0..65535
    float2 acc = *(const float2*)b2;
    #pragma unroll
    for (int zz = 0; zz < 8; zz++) {
        float2 p = *(const float2*)(g_part + zz * (4 * 128 * 128 * 2) + idx * 2);
        acc.x += p.x; acc.y += p.y;
    }
    *(float2*)(out + idx * 2) = acc;
}

extern "C" void kernel_launch(void* const* d_in, const int* in_sizes, int n_in,
                              void* d_out, int out_size)
{
    const float* a  = (const float*)d_in[0];
    const float* b  = (const float*)d_in[1];
    const float* W1 = (const float*)d_in[2];
    const float* b1 = (const float*)d_in[3];
    const float* W2 = (const float*)d_in[4];
    const float* b2 = (const float*)d_in[5];
    float* out = (float*)d_out;

    proj_kernel<<<dim3(32, 12), 128>>>(a, b, W1, b1);
    pair_kernel<<<dim3(4, 4, 8), 256>>>(W2);
    reduce_kernel<<<256, 256>>>(b2, out);
}